// round 13
// baseline (speedup 1.0000x reference)
#include <cuda_runtime.h>
#include <cuda_bf16.h>
#include <math.h>
#include <stdint.h>

// Problem constants
#define BATCH 2
#define SEQ   2048
#define DIM   2048
#define NH    16
#define HD    128
#define M_TOT (BATCH*SEQ)      // 4096
#define QKV_N (3*DIM)          // 6144
#define K3    (3*DIM)          // split-tripled K = 6144

// ---------------------------------------------------------------------------
// Scratch (allocation-free rule: __device__ globals)
// ---------------------------------------------------------------------------
__device__ float g_qkv[M_TOT * QKV_N];            // fp32 qkv   ~100.7 MB
__device__ __nv_bfloat16 g_x3   [M_TOT * K3];     // 50 MB
__device__ __nv_bfloat16 g_wqkv3[QKV_N * K3];     // 75 MB
__device__ __nv_bfloat16 g_attn3[M_TOT * K3];     // 50 MB (written by attention)
__device__ __nv_bfloat16 g_wout3[DIM   * K3];     // 25 MB

// ---------------------------------------------------------------------------
// mma.sync / ldmatrix / cp.async helpers (baseline sm_80+ PTX, works on sm_100)
// ---------------------------------------------------------------------------
#define LDSM4(r0, r1, r2, r3, addr) \
    asm volatile("ldmatrix.sync.aligned.m8n8.x4.shared.b16 {%0,%1,%2,%3}, [%4];" \
                 : "=r"(r0), "=r"(r1), "=r"(r2), "=r"(r3) : "r"(addr))

#define MMA16816(d0, d1, d2, d3, a0, a1, a2, a3, b0, b1) \
    asm volatile("mma.sync.aligned.m16n8k16.row.col.f32.bf16.bf16.f32 " \
                 "{%0,%1,%2,%3}, {%4,%5,%6,%7}, {%8,%9}, {%0,%1,%2,%3};" \
                 : "+f"(d0), "+f"(d1), "+f"(d2), "+f"(d3) \
                 : "r"(a0), "r"(a1), "r"(a2), "r"(a3), "r"(b0), "r"(b1))

#define CP_ASYNC16(dst_u32, src) \
    asm volatile("cp.async.cg.shared.global [%0], [%1], 16;" :: "r"(dst_u32), "l"(src))
#define CP_COMMIT() asm volatile("cp.async.commit_group;" ::: "memory")
#define CP_WAIT(n)  asm volatile("cp.async.wait_group %0;" :: "n"(n) : "memory")

// ---------------------------------------------------------------------------
// split3: fp32 -> 3-block bf16 split along K.
// dst row stride = 3K:  block0 = hi, block1 = (isA ? lo : hi), block2 = (isA ? hi : lo)
// ---------------------------------------------------------------------------
__global__ __launch_bounds__(256)
void split3_kernel(const float* __restrict__ src, __nv_bfloat16* __restrict__ dst,
                   int K, int isA)
{
    int idx = blockIdx.x * blockDim.x + threadIdx.x;
    int k4cnt = K >> 2;
    int r  = idx / k4cnt;
    int k  = (idx - r * k4cnt) << 2;

    float4 v = *(const float4*)&src[(size_t)r * K + k];
    __nv_bfloat16 h0 = __float2bfloat16(v.x), h1 = __float2bfloat16(v.y);
    __nv_bfloat16 h2 = __float2bfloat16(v.z), h3 = __float2bfloat16(v.w);
    __nv_bfloat16 l0 = __float2bfloat16(v.x - __bfloat162float(h0));
    __nv_bfloat16 l1 = __float2bfloat16(v.y - __bfloat162float(h1));
    __nv_bfloat16 l2 = __float2bfloat16(v.z - __bfloat162float(h2));
    __nv_bfloat16 l3 = __float2bfloat16(v.w - __bfloat162float(h3));

    union { __nv_bfloat16 b[4]; uint2 u; } hi, lo;
    hi.b[0]=h0; hi.b[1]=h1; hi.b[2]=h2; hi.b[3]=h3;
    lo.b[0]=l0; lo.b[1]=l1; lo.b[2]=l2; lo.b[3]=l3;

    size_t base = (size_t)r * (3 * K) + k;
    *(uint2*)&dst[base]         = hi.u;
    *(uint2*)&dst[base + K]     = isA ? lo.u : hi.u;
    *(uint2*)&dst[base + 2 * K] = isA ? hi.u : lo.u;
}

// ---------------------------------------------------------------------------
// mma.sync bf16 GEMM: C[M, ldc](fp32) = A3[M, K3] @ B3[N, K3]^T
// Tile 128x128x64, 256 threads (8 warps, 2x4), warp tile 64x32.
// 3-stage cp.async circular pipeline (110.6 KB dynamic smem), 2 CTAs/SM.
// Halved barrier frequency vs BK=32 (96 iters instead of 192).
// ---------------------------------------------------------------------------
#define BK 64
#define ASTR 72                        // padded row stride in bf16 elems
#define NIT (K3 / BK)                  // 96
#define STAGES 3
#define MAT_ELEMS (128 * ASTR)         // 9216 bf16 per matrix per stage
#define STAGE_ELEMS (2 * MAT_ELEMS)    // A + B = 18432
#define GEMM_SMEM (STAGES * STAGE_ELEMS * 2)   // 110592 bytes

__global__ __launch_bounds__(256, 2)
void gemm_mma_kernel(const __nv_bfloat16* __restrict__ A3,
                     const __nv_bfloat16* __restrict__ B3,
                     float* __restrict__ C, int ldc)
{
    extern __shared__ __nv_bfloat16 smem[];

    const int tid  = threadIdx.x;
    const int wid  = tid >> 5;
    const int lane = tid & 31;
    const int warp_m = wid & 1;          // 0..1
    const int warp_n = wid >> 1;         // 0..3
    const int m0 = blockIdx.y * 128;
    const int n0 = blockIdx.x * 128;

    const __nv_bfloat16* Abase = A3 + (size_t)m0 * K3;
    const __nv_bfloat16* Bbase = B3 + (size_t)n0 * K3;

    const uint32_t smem_u32 = (uint32_t)__cvta_generic_to_shared(smem);

    // per-thread load slots: 2048 16B chunks per stage (A 1024 + B 1024), 8 each
    int rowL[8], segL[8], isBL[8];
    uint32_t soff[8];   // element offset within a stage
    #pragma unroll
    for (int r = 0; r < 8; r++) {
        int chunk = tid + r * 256;
        isBL[r] = chunk >> 10;
        int cc  = chunk & 1023;
        rowL[r] = cc >> 3;
        segL[r] = cc & 7;
        soff[r] = isBL[r] * MAT_ELEMS + rowL[r] * ASTR + segL[r] * 8;
    }

    auto load_tile = [&](int it, int st) {
        int k0 = it * BK;
        uint32_t sbase = smem_u32 + (uint32_t)(st * STAGE_ELEMS) * 2;
        #pragma unroll
        for (int r = 0; r < 8; r++) {
            const __nv_bfloat16* src =
                (isBL[r] ? Bbase : Abase) + (size_t)rowL[r] * K3 + k0 + segL[r] * 8;
            CP_ASYNC16(sbase + soff[r] * 2, src);
        }
    };

    float d[4][4][4];
    #pragma unroll
    for (int i = 0; i < 4; i++)
        #pragma unroll
        for (int j = 0; j < 4; j++)
            #pragma unroll
            for (int q = 0; q < 4; q++) d[i][j][q] = 0.f;

    // prologue: fill 2 stages
    load_tile(0, 0); CP_COMMIT();
    load_tile(1, 1); CP_COMMIT();

    const int lrow = lane & 15;
    const int lcol = (lane >> 4) << 3;

    int cur = 0, pf = 2;
    for (int it = 0; it < NIT; it++) {
        CP_WAIT(1);
        __syncthreads();

        // prefetch tile it+2 into the stage freed at iter it-1
        if (it + 2 < NIT) load_tile(it + 2, pf);
        CP_COMMIT();

        const __nv_bfloat16* As = smem + cur * STAGE_ELEMS;
        const __nv_bfloat16* Bs = As + MAT_ELEMS;

        #pragma unroll
        for (int ks = 0; ks < BK; ks += 16) {
            uint32_t a[4][4], b[2][4];
            #pragma unroll
            for (int i = 0; i < 4; i++) {
                uint32_t addr = (uint32_t)__cvta_generic_to_shared(
                    As + (warp_m * 64 + i * 16 + lrow) * ASTR + ks + lcol);
                LDSM4(a[i][0], a[i][1], a[i][2], a[i][3], addr);
            }
            #pragma unroll
            for (int j = 0; j < 2; j++) {
                uint32_t addr = (uint32_t)__cvta_generic_to_shared(
                    Bs + (warp_n * 32 + j * 16 + lrow) * ASTR + ks + lcol);
                LDSM4(b[j][0], b[j][1], b[j][2], b[j][3], addr);
            }
            #pragma unroll
            for (int i = 0; i < 4; i++) {
                #pragma unroll
                for (int jj = 0; jj < 4; jj++) {
                    uint32_t b0 = b[jj >> 1][(jj & 1)];
                    uint32_t b1 = b[jj >> 1][(jj & 1) + 2];
                    MMA16816(d[i][jj][0], d[i][jj][1], d[i][jj][2], d[i][jj][3],
                             a[i][0], a[i][1], a[i][2], a[i][3], b0, b1);
                }
            }
        }

        cur = (cur == 2) ? 0 : cur + 1;
        pf  = (pf  == 2) ? 0 : pf  + 1;
    }

    const int crow = lane >> 2;
    const int ccol = (lane & 3) * 2;
    #pragma unroll
    for (int i = 0; i < 4; i++) {
        #pragma unroll
        for (int jj = 0; jj < 4; jj++) {
            int m = m0 + warp_m * 64 + i * 16 + crow;
            int n = n0 + warp_n * 32 + jj * 8 + ccol;
            *(float2*)&C[(size_t)m * ldc + n] =
                make_float2(d[i][jj][0], d[i][jj][1]);
            *(float2*)&C[(size_t)(m + 8) * ldc + n] =
                make_float2(d[i][jj][2], d[i][jj][3]);
        }
    }
}

// ---------------------------------------------------------------------------
// RoPE (interleaved pairs) in-place on q,k slices of g_qkv (fp32)
// ---------------------------------------------------------------------------
__global__ __launch_bounds__(256)
void rope_kernel(float* __restrict__ qkv, const float* __restrict__ freqs)
{
    int idx = blockIdx.x * blockDim.x + threadIdx.x;   // < 4096*1024
    int m = idx >> 10;
    int p = idx & 1023;
    int t = m & (SEQ - 1);
    int head = p >> 6;
    int j    = p & 63;

    float ang = freqs[t * HD + 2*j];
    float c = cosf(ang);
    float s = sinf(ang);

    size_t base = (size_t)m * QKV_N + head * HD + 2*j;
    float q0 = qkv[base], q1 = qkv[base + 1];
    qkv[base]     = q0 * c - q1 * s;
    qkv[base + 1] = q1 * c + q0 * s;
    float k0 = qkv[base + DIM], k1 = qkv[base + DIM + 1];
    qkv[base + DIM]     = k0 * c - k1 * s;
    qkv[base + DIM + 1] = k1 * c + k0 * s;
}

// ---------------------------------------------------------------------------
// Causal flash attention, fp32 (R10-proven config). BM=128 (8 rows/thread),
// BN=64, smem ~166 KB (1 CTA/SM). Reversed qt order: big blocks first.
// Epilogue writes the 3-block bf16 split layout into g_attn3 (hi | lo | hi).
// ---------------------------------------------------------------------------
#define ATTN_SMEM ((128*132 + 64*132 + 64*132 + 128*68) * 4)   // 169984 B

__global__ __launch_bounds__(256)
void attn_kernel(const float* __restrict__ qkv, __nv_bfloat16* __restrict__ attn3)
{
    constexpr int BM = 128, BN = 64;
    constexpr int KS = 132;
    constexpr int PS = 68;
    const float scale = 0.08838834764831843f;

    extern __shared__ float sm[];
    float* Qs = sm;                    // 128*132
    float* Ks = Qs + BM * KS;          // 64*132
    float* Vs = Ks + BN * KS;          // 64*132
    float* Ps = Vs + BN * KS;          // 128*68

    const int qt   = gridDim.x - 1 - blockIdx.x;   // reversed: big blocks first
    const int head = blockIdx.y;
    const int b    = blockIdx.z;
    const int tid  = threadIdx.x;
    const int ty   = tid >> 4;
    const int tx   = tid & 15;

    const size_t rowstride = QKV_N;
    const size_t qoff = (size_t)head * HD;
    const size_t koff = qoff + DIM;
    const size_t voff = qoff + 2 * DIM;

    // load Q tile (128 rows x 128)
    for (int i = tid; i < BM * 32; i += 256) {
        int r = i >> 5, d4 = (i & 31) * 4;
        size_t g = (size_t)(b * SEQ + qt * BM + r) * rowstride + qoff + d4;
        *(float4*)&Qs[r * KS + d4] = *(const float4*)&qkv[g];
    }

    float acc[8][8];
    #pragma unroll
    for (int r = 0; r < 8; r++)
        #pragma unroll
        for (int j = 0; j < 8; j++) acc[r][j] = 0.f;
    float m_i[8], l_i[8];
    #pragma unroll
    for (int r = 0; r < 8; r++) { m_i[r] = -INFINITY; l_i[r] = 0.f; }

    const int ktmax = 2 * qt + 1;
    for (int kt = 0; kt <= ktmax; kt++) {
        __syncthreads();
        for (int i = tid; i < BN * 32; i += 256) {
            int r = i >> 5, d4 = (i & 31) * 4;
            size_t grow = (size_t)(b * SEQ + kt * BN + r) * rowstride;
            *(float4*)&Ks[r * KS + d4] = *(const float4*)&qkv[grow + koff + d4];
            *(float4*)&Vs[r * KS + d4] = *(const float4*)&qkv[grow + voff + d4];
        }
        __syncthreads();

        // ---- S = Q K^T : 8 rows x 4 cols per thread ----
        float s[8][4];
        #pragma unroll
        for (int r = 0; r < 8; r++)
            #pragma unroll
            for (int j = 0; j < 4; j++) s[r][j] = 0.f;

        for (int d4 = 0; d4 < 32; d4++) {
            float4 kv[4];
            #pragma unroll
            for (int j = 0; j < 4; j++)
                kv[j] = *(float4*)&Ks[(tx + 16*j) * KS + d4*4];
            #pragma unroll
            for (int r = 0; r < 8; r++) {
                float4 qv = *(float4*)&Qs[(ty*8 + r) * KS + d4*4];
                #pragma unroll
                for (int j = 0; j < 4; j++) {
                    s[r][j] = fmaf(qv.x, kv[j].x, s[r][j]);
                    s[r][j] = fmaf(qv.y, kv[j].y, s[r][j]);
                    s[r][j] = fmaf(qv.z, kv[j].z, s[r][j]);
                    s[r][j] = fmaf(qv.w, kv[j].w, s[r][j]);
                }
            }
        }

        // ---- scale + causal mask + online softmax ----
        #pragma unroll
        for (int r = 0; r < 8; r++) {
            int grow = qt * BM + ty*8 + r;
            float rm = -INFINITY;
            #pragma unroll
            for (int j = 0; j < 4; j++) {
                int gcol = kt * BN + tx + 16*j;
                s[r][j] = (gcol > grow) ? -INFINITY : s[r][j] * scale;
                rm = fmaxf(rm, s[r][j]);
            }
            #pragma unroll
            for (int off = 8; off >= 1; off >>= 1)
                rm = fmaxf(rm, __shfl_xor_sync(0xffffffffu, rm, off));
            float m_new = fmaxf(m_i[r], rm);
            float factor = __expf(m_i[r] - m_new);
            float psum = 0.f;
            #pragma unroll
            for (int j = 0; j < 4; j++) {
                float pv = __expf(s[r][j] - m_new);
                s[r][j] = pv;
                psum += pv;
            }
            #pragma unroll
            for (int off = 8; off >= 1; off >>= 1)
                psum += __shfl_xor_sync(0xffffffffu, psum, off);
            l_i[r] = l_i[r] * factor + psum;
            m_i[r] = m_new;
            #pragma unroll
            for (int j = 0; j < 8; j++) acc[r][j] *= factor;
            #pragma unroll
            for (int j = 0; j < 4; j++)
                Ps[(ty*8 + r) * PS + tx + 16*j] = s[r][j];
        }
        __syncthreads();

        // ---- O += P V  (8 rows, cols tx*8..+7) ----
        for (int c = 0; c < BN; c++) {
            float4 v0 = *(float4*)&Vs[c * KS + tx*8];
            float4 v1 = *(float4*)&Vs[c * KS + tx*8 + 4];
            #pragma unroll
            for (int r = 0; r < 8; r++) {
                float pv = Ps[(ty*8 + r) * PS + c];
                acc[r][0] = fmaf(pv, v0.x, acc[r][0]);
                acc[r][1] = fmaf(pv, v0.y, acc[r][1]);
                acc[r][2] = fmaf(pv, v0.z, acc[r][2]);
                acc[r][3] = fmaf(pv, v0.w, acc[r][3]);
                acc[r][4] = fmaf(pv, v1.x, acc[r][4]);
                acc[r][5] = fmaf(pv, v1.y, acc[r][5]);
                acc[r][6] = fmaf(pv, v1.z, acc[r][6]);
                acc[r][7] = fmaf(pv, v1.w, acc[r][7]);
            }
        }
    }

    // ---- normalize + fused 3-block bf16 split store: [hi | lo | hi] ----
    #pragma unroll
    for (int r = 0; r < 8; r++) {
        float inv = 1.f / l_i[r];
        union { __nv_bfloat16 b[8]; uint4 u; } hi, lo;
        #pragma unroll
        for (int j = 0; j < 8; j++) {
            float o = acc[r][j] * inv;
            __nv_bfloat16 h = __float2bfloat16(o);
            hi.b[j] = h;
            lo.b[j] = __float2bfloat16(o - __bfloat162float(h));
        }
        size_t row  = (size_t)(b * SEQ + qt * BM + ty*8 + r);
        size_t base = row * (3 * DIM) + head * HD + tx * 8;
        *(uint4*)&attn3[base]           = hi.u;
        *(uint4*)&attn3[base + DIM]     = lo.u;
        *(uint4*)&attn3[base + 2 * DIM] = hi.u;
    }
}

// ---------------------------------------------------------------------------
// launcher
// ---------------------------------------------------------------------------
extern "C" void kernel_launch(void* const* d_in, const int* in_sizes, int n_in,
                              void* d_out, int out_size)
{
    const float* x     = (const float*)d_in[0];   // [2,2048,2048]
    const float* freqs = (const float*)d_in[1];   // [2048,128]
    const float* Wqkv  = (const float*)d_in[2];   // [6144,2048]
    const float* Wout  = (const float*)d_in[3];   // [2048,2048]
    float* out = (float*)d_out;                   // [2,2048,2048]

    float *qkv;
    __nv_bfloat16 *x3, *wqkv3, *attn3, *wout3;
    cudaGetSymbolAddress((void**)&qkv,   g_qkv);
    cudaGetSymbolAddress((void**)&x3,    g_x3);
    cudaGetSymbolAddress((void**)&wqkv3, g_wqkv3);
    cudaGetSymbolAddress((void**)&attn3, g_attn3);
    cudaGetSymbolAddress((void**)&wout3, g_wout3);

    cudaFuncSetAttribute(gemm_mma_kernel,
                         cudaFuncAttributeMaxDynamicSharedMemorySize, GEMM_SMEM);
    cudaFuncSetAttribute(attn_kernel,
                         cudaFuncAttributeMaxDynamicSharedMemorySize, ATTN_SMEM);

    // 1) bf16 3-split conversions for stage-1 GEMM
    split3_kernel<<<(M_TOT * (DIM/4)) / 256, 256>>>(x,    x3,    DIM, 1);
    split3_kernel<<<(QKV_N * (DIM/4)) / 256, 256>>>(Wqkv, wqkv3, DIM, 0);

    // 2) QKV projection on tensor cores (128x128x64 tile, 3-stage, 2 CTA/SM)
    gemm_mma_kernel<<<dim3(QKV_N/128, M_TOT/128), 256, GEMM_SMEM>>>(x3, wqkv3, qkv, QKV_N);

    // 3) RoPE in place (fp32)
    rope_kernel<<<(M_TOT * 1024) / 256, 256>>>(qkv, freqs);

    // 4) causal flash attention (fp32, BM=128, R10 config) -> g_attn3
    attn_kernel<<<dim3(SEQ/128, NH, BATCH), 256, ATTN_SMEM>>>(qkv, attn3);

    // 5) weight conversion for stage-2 GEMM
    split3_kernel<<<(DIM * (DIM/4)) / 256, 256>>>(Wout, wout3, DIM, 0);

    // 6) output projection on tensor cores
    gemm_mma_kernel<<<dim3(DIM/128, M_TOT/128), 256, GEMM_SMEM>>>(attn3, wout3, out, DIM);
}

// round 14
// speedup vs baseline: 1.5698x; 1.5698x over previous
#include <cuda_runtime.h>
#include <cuda_bf16.h>
#include <cuda_fp16.h>
#include <math.h>
#include <stdint.h>

// Problem constants
#define BATCH 2
#define SEQ   2048
#define DIM   2048
#define NH    16
#define HD    128
#define M_TOT (BATCH*SEQ)      // 4096
#define QKV_N (3*DIM)          // 6144
#define K3    (3*DIM)          // split-tripled K = 6144

// ---------------------------------------------------------------------------
// Scratch (allocation-free rule: __device__ globals)
// ---------------------------------------------------------------------------
__device__ float g_qkv[M_TOT * QKV_N];            // fp32 qkv   ~100.7 MB
__device__ __nv_bfloat16 g_x3   [M_TOT * K3];     // 50 MB
__device__ __nv_bfloat16 g_wqkv3[QKV_N * K3];     // 75 MB
__device__ __nv_bfloat16 g_attn3[M_TOT * K3];     // 50 MB (written by attention)
__device__ __nv_bfloat16 g_wout3[DIM   * K3];     // 25 MB
__device__ __half g_q2[BATCH * NH * SEQ * 256];   // 33.5 MB  [qh(128)|ql(128)]
__device__ __half g_k2[BATCH * NH * SEQ * 256];   // 33.5 MB  [kh(128)|kl(128)]
__device__ __half g_vt[BATCH * NH * HD * SEQ];    // 16.8 MB  transposed [hd][t]

// ---------------------------------------------------------------------------
// mma.sync / ldmatrix / cp.async helpers (baseline sm_80+ PTX, works on sm_100)
// ---------------------------------------------------------------------------
#define LDSM4(r0, r1, r2, r3, addr) \
    asm volatile("ldmatrix.sync.aligned.m8n8.x4.shared.b16 {%0,%1,%2,%3}, [%4];" \
                 : "=r"(r0), "=r"(r1), "=r"(r2), "=r"(r3) : "r"(addr))

#define MMA16816(d0, d1, d2, d3, a0, a1, a2, a3, b0, b1) \
    asm volatile("mma.sync.aligned.m16n8k16.row.col.f32.bf16.bf16.f32 " \
                 "{%0,%1,%2,%3}, {%4,%5,%6,%7}, {%8,%9}, {%0,%1,%2,%3};" \
                 : "+f"(d0), "+f"(d1), "+f"(d2), "+f"(d3) \
                 : "r"(a0), "r"(a1), "r"(a2), "r"(a3), "r"(b0), "r"(b1))

#define MMAF16(d0, d1, d2, d3, a0, a1, a2, a3, b0, b1) \
    asm volatile("mma.sync.aligned.m16n8k16.row.col.f32.f16.f16.f32 " \
                 "{%0,%1,%2,%3}, {%4,%5,%6,%7}, {%8,%9}, {%0,%1,%2,%3};" \
                 : "+f"(d0), "+f"(d1), "+f"(d2), "+f"(d3) \
                 : "r"(a0), "r"(a1), "r"(a2), "r"(a3), "r"(b0), "r"(b1))

#define CP_ASYNC16(dst_u32, src) \
    asm volatile("cp.async.cg.shared.global [%0], [%1], 16;" :: "r"(dst_u32), "l"(src))
#define CP_COMMIT() asm volatile("cp.async.commit_group;" ::: "memory")
#define CP_WAIT(n)  asm volatile("cp.async.wait_group %0;" :: "n"(n) : "memory")

// ---------------------------------------------------------------------------
// split3: fp32 -> 3-block bf16 split along K (GEMM operands)
// ---------------------------------------------------------------------------
__global__ __launch_bounds__(256)
void split3_kernel(const float* __restrict__ src, __nv_bfloat16* __restrict__ dst,
                   int K, int isA)
{
    int idx = blockIdx.x * blockDim.x + threadIdx.x;
    int k4cnt = K >> 2;
    int r  = idx / k4cnt;
    int k  = (idx - r * k4cnt) << 2;

    float4 v = *(const float4*)&src[(size_t)r * K + k];
    __nv_bfloat16 h0 = __float2bfloat16(v.x), h1 = __float2bfloat16(v.y);
    __nv_bfloat16 h2 = __float2bfloat16(v.z), h3 = __float2bfloat16(v.w);
    __nv_bfloat16 l0 = __float2bfloat16(v.x - __bfloat162float(h0));
    __nv_bfloat16 l1 = __float2bfloat16(v.y - __bfloat162float(h1));
    __nv_bfloat16 l2 = __float2bfloat16(v.z - __bfloat162float(h2));
    __nv_bfloat16 l3 = __float2bfloat16(v.w - __bfloat162float(h3));

    union { __nv_bfloat16 b[4]; uint2 u; } hi, lo;
    hi.b[0]=h0; hi.b[1]=h1; hi.b[2]=h2; hi.b[3]=h3;
    lo.b[0]=l0; lo.b[1]=l1; lo.b[2]=l2; lo.b[3]=l3;

    size_t base = (size_t)r * (3 * K) + k;
    *(uint2*)&dst[base]         = hi.u;
    *(uint2*)&dst[base + K]     = isA ? lo.u : hi.u;
    *(uint2*)&dst[base + 2 * K] = isA ? hi.u : lo.u;
}

// ---------------------------------------------------------------------------
// mma.sync bf16 GEMM (R13 config): 128x128x64, 3-stage, 2 CTA/SM
// ---------------------------------------------------------------------------
#define BK 64
#define ASTR 72
#define NIT (K3 / BK)
#define STAGES 3
#define MAT_ELEMS (128 * ASTR)
#define STAGE_ELEMS (2 * MAT_ELEMS)
#define GEMM_SMEM (STAGES * STAGE_ELEMS * 2)

__global__ __launch_bounds__(256, 2)
void gemm_mma_kernel(const __nv_bfloat16* __restrict__ A3,
                     const __nv_bfloat16* __restrict__ B3,
                     float* __restrict__ C, int ldc)
{
    extern __shared__ __nv_bfloat16 smem[];

    const int tid  = threadIdx.x;
    const int wid  = tid >> 5;
    const int lane = tid & 31;
    const int warp_m = wid & 1;
    const int warp_n = wid >> 1;
    const int m0 = blockIdx.y * 128;
    const int n0 = blockIdx.x * 128;

    const __nv_bfloat16* Abase = A3 + (size_t)m0 * K3;
    const __nv_bfloat16* Bbase = B3 + (size_t)n0 * K3;

    const uint32_t smem_u32 = (uint32_t)__cvta_generic_to_shared(smem);

    int rowL[8], segL[8], isBL[8];
    uint32_t soff[8];
    #pragma unroll
    for (int r = 0; r < 8; r++) {
        int chunk = tid + r * 256;
        isBL[r] = chunk >> 10;
        int cc  = chunk & 1023;
        rowL[r] = cc >> 3;
        segL[r] = cc & 7;
        soff[r] = isBL[r] * MAT_ELEMS + rowL[r] * ASTR + segL[r] * 8;
    }

    auto load_tile = [&](int it, int st) {
        int k0 = it * BK;
        uint32_t sbase = smem_u32 + (uint32_t)(st * STAGE_ELEMS) * 2;
        #pragma unroll
        for (int r = 0; r < 8; r++) {
            const __nv_bfloat16* src =
                (isBL[r] ? Bbase : Abase) + (size_t)rowL[r] * K3 + k0 + segL[r] * 8;
            CP_ASYNC16(sbase + soff[r] * 2, src);
        }
    };

    float d[4][4][4];
    #pragma unroll
    for (int i = 0; i < 4; i++)
        #pragma unroll
        for (int j = 0; j < 4; j++)
            #pragma unroll
            for (int q = 0; q < 4; q++) d[i][j][q] = 0.f;

    load_tile(0, 0); CP_COMMIT();
    load_tile(1, 1); CP_COMMIT();

    const int lrow = lane & 15;
    const int lcol = (lane >> 4) << 3;

    int cur = 0, pf = 2;
    for (int it = 0; it < NIT; it++) {
        CP_WAIT(1);
        __syncthreads();

        if (it + 2 < NIT) load_tile(it + 2, pf);
        CP_COMMIT();

        const __nv_bfloat16* As = smem + cur * STAGE_ELEMS;
        const __nv_bfloat16* Bs = As + MAT_ELEMS;

        #pragma unroll
        for (int ks = 0; ks < BK; ks += 16) {
            uint32_t a[4][4], b[2][4];
            #pragma unroll
            for (int i = 0; i < 4; i++) {
                uint32_t addr = (uint32_t)__cvta_generic_to_shared(
                    As + (warp_m * 64 + i * 16 + lrow) * ASTR + ks + lcol);
                LDSM4(a[i][0], a[i][1], a[i][2], a[i][3], addr);
            }
            #pragma unroll
            for (int j = 0; j < 2; j++) {
                uint32_t addr = (uint32_t)__cvta_generic_to_shared(
                    Bs + (warp_n * 32 + j * 16 + lrow) * ASTR + ks + lcol);
                LDSM4(b[j][0], b[j][1], b[j][2], b[j][3], addr);
            }
            #pragma unroll
            for (int i = 0; i < 4; i++) {
                #pragma unroll
                for (int jj = 0; jj < 4; jj++) {
                    uint32_t b0 = b[jj >> 1][(jj & 1)];
                    uint32_t b1 = b[jj >> 1][(jj & 1) + 2];
                    MMA16816(d[i][jj][0], d[i][jj][1], d[i][jj][2], d[i][jj][3],
                             a[i][0], a[i][1], a[i][2], a[i][3], b0, b1);
                }
            }
        }

        cur = (cur == 2) ? 0 : cur + 1;
        pf  = (pf  == 2) ? 0 : pf  + 1;
    }

    const int crow = lane >> 2;
    const int ccol = (lane & 3) * 2;
    #pragma unroll
    for (int i = 0; i < 4; i++) {
        #pragma unroll
        for (int jj = 0; jj < 4; jj++) {
            int m = m0 + warp_m * 64 + i * 16 + crow;
            int n = n0 + warp_n * 32 + jj * 8 + ccol;
            *(float2*)&C[(size_t)m * ldc + n] =
                make_float2(d[i][jj][0], d[i][jj][1]);
            *(float2*)&C[(size_t)(m + 8) * ldc + n] =
                make_float2(d[i][jj][2], d[i][jj][3]);
        }
    }
}

// ---------------------------------------------------------------------------
// prep: RoPE q,k -> fp16 2-term split [hi|lo]; V -> fp16 transposed [hd][t].
// grid (SEQ/64, NH, BATCH), 256 threads.
// ---------------------------------------------------------------------------
__global__ __launch_bounds__(256)
void prep_kernel(const float* __restrict__ qkv, const float* __restrict__ freqs,
                 __half* __restrict__ q2, __half* __restrict__ k2,
                 __half* __restrict__ vt)
{
    __shared__ float sv[64 * 128];
    const int tt = blockIdx.x, h = blockIdx.y, b = blockIdx.z;
    const int tid = threadIdx.x;
    const size_t bh = (size_t)b * NH + h;

    // stage V tile [64 t][128 hd]
    for (int i = tid; i < 64 * 32; i += 256) {
        int r = i >> 5, c4 = (i & 31) * 4;
        *(float4*)&sv[r * 128 + c4] =
            *(const float4*)&qkv[(size_t)(b * SEQ + tt * 64 + r) * QKV_N + 2 * DIM + h * HD + c4];
    }

    // rope q,k and write fp16 2-term split rows [hi(128) | lo(128)]
    for (int i = tid; i < 64 * 64; i += 256) {
        int r = i >> 6, j = i & 63;
        int t = tt * 64 + r;
        size_t base = (size_t)(b * SEQ + t) * QKV_N + h * HD + 2 * j;
        float q0 = qkv[base],        q1 = qkv[base + 1];
        float k0 = qkv[base + DIM],  k1 = qkv[base + DIM + 1];
        float ang = freqs[t * HD + 2 * j];
        float c = cosf(ang), s = sinf(ang);
        float qr0 = q0 * c - q1 * s, qr1 = q1 * c + q0 * s;
        float kr0 = k0 * c - k1 * s, kr1 = k1 * c + k0 * s;

        union { __half h[2]; uint32_t u; } p;
        size_t row = (bh * SEQ + t) * 256;

        __half qh0 = __float2half(qr0), qh1 = __float2half(qr1);
        p.h[0] = qh0; p.h[1] = qh1;                     *(uint32_t*)&q2[row + 2*j] = p.u;
        p.h[0] = __float2half(qr0 - __half2float(qh0));
        p.h[1] = __float2half(qr1 - __half2float(qh1)); *(uint32_t*)&q2[row + 128 + 2*j] = p.u;

        __half kh0 = __float2half(kr0), kh1 = __float2half(kr1);
        p.h[0] = kh0; p.h[1] = kh1;                     *(uint32_t*)&k2[row + 2*j] = p.u;
        p.h[0] = __float2half(kr0 - __half2float(kh0));
        p.h[1] = __float2half(kr1 - __half2float(kh1)); *(uint32_t*)&k2[row + 128 + 2*j] = p.u;
    }
    __syncthreads();

    // transposed V write: row = hd, cols = t
    for (int i = tid; i < 128 * 32; i += 256) {
        int hd = i >> 5, c = i & 31;
        union { __half h[2]; uint32_t u; } p;
        p.h[0] = __float2half(sv[(2 * c)     * 128 + hd]);
        p.h[1] = __float2half(sv[(2 * c + 1) * 128 + hd]);
        *(uint32_t*)&vt[(bh * 128 + hd) * SEQ + tt * 64 + 2 * c] = p.u;
    }
}

// ---------------------------------------------------------------------------
// Tensor-core causal flash attention (fp16 HMMA).
// BM=128 (8 warps x m16), BN=64. S = qh*kh + qh*kl + ql*kh (fp16 2-term split),
// PV in plain fp16 (P from register fragments, FA2 repack). Double-buffered
// cp.async K/V. Epilogue writes 3-block bf16 split [hi|lo|hi] into g_attn3.
// ---------------------------------------------------------------------------
#define AQ_STR 264                       // half stride (256 + 8 pad)
#define AV_STR 72                        // half stride (64 + 8 pad)
#define Q2_ELEM (128 * AQ_STR)           // 33792 half
#define K2_ELEM (64 * AQ_STR)            // 16896 half
#define VT_ELEM (128 * AV_STR)           // 9216 half
#define ATTN_SMEM ((Q2_ELEM + 2 * K2_ELEM + 2 * VT_ELEM) * 2)   // 172032 B

__global__ __launch_bounds__(256)
void attn_tc_kernel(const __half* __restrict__ q2, const __half* __restrict__ k2,
                    const __half* __restrict__ vt, __nv_bfloat16* __restrict__ attn3)
{
    const float scale = 0.08838834764831843f;

    extern __shared__ __half sh[];
    __half* Qs  = sh;                       // [128][AQ_STR]
    __half* Kst = Qs + Q2_ELEM;             // 2 x [64][AQ_STR]
    __half* Vst = Kst + 2 * K2_ELEM;        // 2 x [128][AV_STR]

    const int qt   = gridDim.x - 1 - blockIdx.x;
    const int head = blockIdx.y;
    const int b    = blockIdx.z;
    const int tid  = threadIdx.x;
    const int w    = tid >> 5;
    const int lane = tid & 31;
    const int r0   = lane >> 2;             // 0..7
    const int c0   = (lane & 3) * 2;        // 0,2,4,6
    const size_t bh = (size_t)b * NH + head;

    const uint32_t sbase = (uint32_t)__cvta_generic_to_shared(sh);
    const uint32_t qs_u  = sbase;
    const uint32_t ks_u  = sbase + Q2_ELEM * 2;
    const uint32_t vs_u  = ks_u + 2 * K2_ELEM * 2;

    // ---- cp.async loaders ----
    // Q: 4096 chunks (16/thread): row=c>>5, seg=c&31
    auto loadQ = [&]() {
        #pragma unroll
        for (int i = 0; i < 16; i++) {
            int ch = tid + i * 256;
            int row = ch >> 5, seg = ch & 31;
            const __half* src = q2 + (bh * SEQ + qt * 128 + row) * 256 + seg * 8;
            CP_ASYNC16(qs_u + (uint32_t)(row * AQ_STR + seg * 8) * 2, src);
        }
    };
    // K: 2048 chunks (8/thread); V: 1024 chunks (4/thread)
    auto loadKV = [&](int kt, int buf) {
        uint32_t kb = ks_u + (uint32_t)(buf * K2_ELEM) * 2;
        #pragma unroll
        for (int i = 0; i < 8; i++) {
            int ch = tid + i * 256;
            int row = ch >> 5, seg = ch & 31;
            const __half* src = k2 + (bh * SEQ + kt * 64 + row) * 256 + seg * 8;
            CP_ASYNC16(kb + (uint32_t)(row * AQ_STR + seg * 8) * 2, src);
        }
        uint32_t vb = vs_u + (uint32_t)(buf * VT_ELEM) * 2;
        #pragma unroll
        for (int i = 0; i < 4; i++) {
            int ch = tid + i * 256;
            int row = ch >> 3, seg = ch & 7;
            const __half* src = vt + (bh * 128 + row) * SEQ + kt * 64 + seg * 8;
            CP_ASYNC16(vb + (uint32_t)(row * AV_STR + seg * 8) * 2, src);
        }
    };

    loadQ();
    loadKV(0, 0);
    CP_COMMIT();

    float o[16][4];
    #pragma unroll
    for (int j = 0; j < 16; j++)
        #pragma unroll
        for (int q = 0; q < 4; q++) o[j][q] = 0.f;
    float m_i[2] = { -INFINITY, -INFINITY };
    float l_i[2] = { 0.f, 0.f };

    const int grow0 = qt * 128 + w * 16 + r0;
    const int grow1 = grow0 + 8;
    const int ktmax = 2 * qt + 1;

    for (int kt = 0; kt <= ktmax; kt++) {
        const int cur = kt & 1;
        CP_WAIT(0);
        __syncthreads();
        if (kt < ktmax) { loadKV(kt + 1, cur ^ 1); CP_COMMIT(); }

        const __half* Ks = Kst + cur * K2_ELEM;
        const __half* Vs = Vst + cur * VT_ELEM;

        // ---- S = 3-pass fp16 split mma ----
        float s[8][4];
        #pragma unroll
        for (int jn = 0; jn < 8; jn++)
            #pragma unroll
            for (int q = 0; q < 4; q++) s[jn][q] = 0.f;

        #pragma unroll
        for (int j = 0; j < 24; j++) {
            const int qoff = (j < 16) ? (j & 7) * 16 : 128 + (j - 16) * 16;
            const int koff = (j < 8) ? j * 16 : ((j < 16) ? 128 + (j - 8) * 16 : (j - 16) * 16);
            const __half* qa = Qs + (w * 16 + r0) * AQ_STR + qoff + c0;
            uint32_t a0 = *(const uint32_t*)qa;
            uint32_t a1 = *(const uint32_t*)(qa + 8 * AQ_STR);
            uint32_t a2 = *(const uint32_t*)(qa + 8);
            uint32_t a3 = *(const uint32_t*)(qa + 8 * AQ_STR + 8);
            #pragma unroll
            for (int jn = 0; jn < 8; jn++) {
                const __half* kb = Ks + (jn * 8 + r0) * AQ_STR + koff + c0;
                uint32_t b0 = *(const uint32_t*)kb;
                uint32_t b1 = *(const uint32_t*)(kb + 8);
                MMAF16(s[jn][0], s[jn][1], s[jn][2], s[jn][3], a0, a1, a2, a3, b0, b1);
            }
        }

        // ---- scale + causal mask + online softmax ----
        float rm0 = -INFINITY, rm1 = -INFINITY;
        #pragma unroll
        for (int jn = 0; jn < 8; jn++) {
            int gcol = kt * 64 + jn * 8 + c0;
            s[jn][0] = (gcol     > grow0) ? -INFINITY : s[jn][0] * scale;
            s[jn][1] = (gcol + 1 > grow0) ? -INFINITY : s[jn][1] * scale;
            s[jn][2] = (gcol     > grow1) ? -INFINITY : s[jn][2] * scale;
            s[jn][3] = (gcol + 1 > grow1) ? -INFINITY : s[jn][3] * scale;
            rm0 = fmaxf(rm0, fmaxf(s[jn][0], s[jn][1]));
            rm1 = fmaxf(rm1, fmaxf(s[jn][2], s[jn][3]));
        }
        rm0 = fmaxf(rm0, __shfl_xor_sync(0xffffffffu, rm0, 1));
        rm0 = fmaxf(rm0, __shfl_xor_sync(0xffffffffu, rm0, 2));
        rm1 = fmaxf(rm1, __shfl_xor_sync(0xffffffffu, rm1, 1));
        rm1 = fmaxf(rm1, __shfl_xor_sync(0xffffffffu, rm1, 2));

        float mn0 = fmaxf(m_i[0], rm0), mn1 = fmaxf(m_i[1], rm1);
        float f0 = __expf(m_i[0] - mn0), f1 = __expf(m_i[1] - mn1);
        float ps0 = 0.f, ps1 = 0.f;
        #pragma unroll
        for (int jn = 0; jn < 8; jn++) {
            s[jn][0] = __expf(s[jn][0] - mn0);
            s[jn][1] = __expf(s[jn][1] - mn0);
            s[jn][2] = __expf(s[jn][2] - mn1);
            s[jn][3] = __expf(s[jn][3] - mn1);
            ps0 += s[jn][0] + s[jn][1];
            ps1 += s[jn][2] + s[jn][3];
        }
        ps0 += __shfl_xor_sync(0xffffffffu, ps0, 1);
        ps0 += __shfl_xor_sync(0xffffffffu, ps0, 2);
        ps1 += __shfl_xor_sync(0xffffffffu, ps1, 1);
        ps1 += __shfl_xor_sync(0xffffffffu, ps1, 2);
        l_i[0] = l_i[0] * f0 + ps0;  m_i[0] = mn0;
        l_i[1] = l_i[1] * f1 + ps1;  m_i[1] = mn1;
        #pragma unroll
        for (int j = 0; j < 16; j++) {
            o[j][0] *= f0; o[j][1] *= f0; o[j][2] *= f1; o[j][3] *= f1;
        }

        // ---- PV: P fragments from registers (FA2 repack), V fp16 B-frags ----
        #pragma unroll
        for (int kt2 = 0; kt2 < 4; kt2++) {
            union { __half2 h; uint32_t u; } pa0, pa1, pa2, pa3;
            pa0.h = __floats2half2_rn(s[2*kt2][0],     s[2*kt2][1]);
            pa1.h = __floats2half2_rn(s[2*kt2][2],     s[2*kt2][3]);
            pa2.h = __floats2half2_rn(s[2*kt2 + 1][0], s[2*kt2 + 1][1]);
            pa3.h = __floats2half2_rn(s[2*kt2 + 1][2], s[2*kt2 + 1][3]);
            #pragma unroll
            for (int jn2 = 0; jn2 < 16; jn2++) {
                const __half* vb = Vs + (jn2 * 8 + r0) * AV_STR + kt2 * 16 + c0;
                uint32_t b0 = *(const uint32_t*)vb;
                uint32_t b1 = *(const uint32_t*)(vb + 8);
                MMAF16(o[jn2][0], o[jn2][1], o[jn2][2], o[jn2][3],
                       pa0.u, pa1.u, pa2.u, pa3.u, b0, b1);
            }
        }
    }

    // ---- epilogue: normalize + 3-block bf16 split [hi | lo | hi] ----
    float inv0 = 1.f / l_i[0], inv1 = 1.f / l_i[1];
    size_t row0 = (size_t)(b * SEQ + grow0);
    size_t row1 = (size_t)(b * SEQ + grow1);
    #pragma unroll
    for (int jn2 = 0; jn2 < 16; jn2++) {
        int hd = head * HD + jn2 * 8 + c0;
        float v00 = o[jn2][0] * inv0, v01 = o[jn2][1] * inv0;
        float v10 = o[jn2][2] * inv1, v11 = o[jn2][3] * inv1;

        union { __nv_bfloat16 b[2]; uint32_t u; } hi, lo;
        __nv_bfloat16 h0, h1;

        h0 = __float2bfloat16(v00); h1 = __float2bfloat16(v01);
        hi.b[0] = h0; hi.b[1] = h1;
        lo.b[0] = __float2bfloat16(v00 - __bfloat162float(h0));
        lo.b[1] = __float2bfloat16(v01 - __bfloat162float(h1));
        size_t base0 = row0 * (3 * DIM) + hd;
        *(uint32_t*)&attn3[base0]           = hi.u;
        *(uint32_t*)&attn3[base0 + DIM]     = lo.u;
        *(uint32_t*)&attn3[base0 + 2*DIM]   = hi.u;

        h0 = __float2bfloat16(v10); h1 = __float2bfloat16(v11);
        hi.b[0] = h0; hi.b[1] = h1;
        lo.b[0] = __float2bfloat16(v10 - __bfloat162float(h0));
        lo.b[1] = __float2bfloat16(v11 - __bfloat162float(h1));
        size_t base1 = row1 * (3 * DIM) + hd;
        *(uint32_t*)&attn3[base1]           = hi.u;
        *(uint32_t*)&attn3[base1 + DIM]     = lo.u;
        *(uint32_t*)&attn3[base1 + 2*DIM]   = hi.u;
    }
}

// ---------------------------------------------------------------------------
// launcher
// ---------------------------------------------------------------------------
extern "C" void kernel_launch(void* const* d_in, const int* in_sizes, int n_in,
                              void* d_out, int out_size)
{
    const float* x     = (const float*)d_in[0];
    const float* freqs = (const float*)d_in[1];
    const float* Wqkv  = (const float*)d_in[2];
    const float* Wout  = (const float*)d_in[3];
    float* out = (float*)d_out;

    float *qkv;
    __nv_bfloat16 *x3, *wqkv3, *attn3, *wout3;
    __half *q2, *k2, *vt;
    cudaGetSymbolAddress((void**)&qkv,   g_qkv);
    cudaGetSymbolAddress((void**)&x3,    g_x3);
    cudaGetSymbolAddress((void**)&wqkv3, g_wqkv3);
    cudaGetSymbolAddress((void**)&attn3, g_attn3);
    cudaGetSymbolAddress((void**)&wout3, g_wout3);
    cudaGetSymbolAddress((void**)&q2,    g_q2);
    cudaGetSymbolAddress((void**)&k2,    g_k2);
    cudaGetSymbolAddress((void**)&vt,    g_vt);

    cudaFuncSetAttribute(gemm_mma_kernel,
                         cudaFuncAttributeMaxDynamicSharedMemorySize, GEMM_SMEM);
    cudaFuncSetAttribute(attn_tc_kernel,
                         cudaFuncAttributeMaxDynamicSharedMemorySize, ATTN_SMEM);

    // 1) bf16 3-split conversions for stage-1 GEMM
    split3_kernel<<<(M_TOT * (DIM/4)) / 256, 256>>>(x,    x3,    DIM, 1);
    split3_kernel<<<(QKV_N * (DIM/4)) / 256, 256>>>(Wqkv, wqkv3, DIM, 0);

    // 2) QKV projection (tensor cores)
    gemm_mma_kernel<<<dim3(QKV_N/128, M_TOT/128), 256, GEMM_SMEM>>>(x3, wqkv3, qkv, QKV_N);

    // 3) prep: rope -> fp16 split q2/k2, transposed fp16 V
    prep_kernel<<<dim3(SEQ/64, NH, BATCH), 256>>>(qkv, freqs, q2, k2, vt);

    // 4) tensor-core causal flash attention -> g_attn3 (bf16 3-split)
    attn_tc_kernel<<<dim3(SEQ/128, NH, BATCH), 256, ATTN_SMEM>>>(q2, k2, vt, attn3);

    // 5) weight conversion for stage-2 GEMM
    split3_kernel<<<(DIM * (DIM/4)) / 256, 256>>>(Wout, wout3, DIM, 0);

    // 6) output projection (tensor cores)
    gemm_mma_kernel<<<dim3(DIM/128, M_TOT/128), 256, GEMM_SMEM>>>(attn3, wout3, out, DIM);
}

// round 15
// speedup vs baseline: 2.1211x; 1.3511x over previous
#include <cuda_runtime.h>
#include <cuda_bf16.h>
#include <cuda_fp16.h>
#include <math.h>
#include <stdint.h>

// Problem constants
#define BATCH 2
#define SEQ   2048
#define DIM   2048
#define NH    16
#define HD    128
#define M_TOT (BATCH*SEQ)      // 4096
#define QKV_N (3*DIM)          // 6144
#define K2    (2*DIM)          // fp16 2-term split K = 4096

// ---------------------------------------------------------------------------
// Scratch (allocation-free rule: __device__ globals)
// ---------------------------------------------------------------------------
__device__ float g_qkv[M_TOT * QKV_N];            // fp32 qkv   ~100.7 MB
__device__ __half g_x2   [M_TOT * K2];            // 33.5 MB  [hi|lo]
__device__ __half g_wqkv2[QKV_N * K2];            // 50 MB    [hi|hi]
__device__ __half g_attn2[M_TOT * K2];            // 33.5 MB  [hi|lo] (from attention)
__device__ __half g_wout2[DIM   * K2];            // 16.8 MB  [hi|hi]
__device__ __half g_q2[BATCH * NH * SEQ * 256];   // 33.5 MB  [qh(128)|ql(128)]
__device__ __half g_k2[BATCH * NH * SEQ * 256];   // 33.5 MB  [kh(128)|kl(128)]
__device__ __half g_vt[BATCH * NH * HD * SEQ];    // 16.8 MB  transposed [hd][t]

// ---------------------------------------------------------------------------
// mma.sync / ldmatrix / cp.async helpers (baseline sm_80+ PTX, works on sm_100)
// ---------------------------------------------------------------------------
#define LDSM4(r0, r1, r2, r3, addr) \
    asm volatile("ldmatrix.sync.aligned.m8n8.x4.shared.b16 {%0,%1,%2,%3}, [%4];" \
                 : "=r"(r0), "=r"(r1), "=r"(r2), "=r"(r3) : "r"(addr))

#define MMAF16(d0, d1, d2, d3, a0, a1, a2, a3, b0, b1) \
    asm volatile("mma.sync.aligned.m16n8k16.row.col.f32.f16.f16.f32 " \
                 "{%0,%1,%2,%3}, {%4,%5,%6,%7}, {%8,%9}, {%0,%1,%2,%3};" \
                 : "+f"(d0), "+f"(d1), "+f"(d2), "+f"(d3) \
                 : "r"(a0), "r"(a1), "r"(a2), "r"(a3), "r"(b0), "r"(b1))

#define CP_ASYNC16(dst_u32, src) \
    asm volatile("cp.async.cg.shared.global [%0], [%1], 16;" :: "r"(dst_u32), "l"(src))
#define CP_COMMIT() asm volatile("cp.async.commit_group;" ::: "memory")
#define CP_WAIT(n)  asm volatile("cp.async.wait_group %0;" :: "n"(n) : "memory")

// ---------------------------------------------------------------------------
// split2: fp32 -> 2-block fp16 split along K.
// dst row stride = 2K:  block0 = hi, block1 = (isA ? lo : hi)
// ---------------------------------------------------------------------------
__global__ __launch_bounds__(256)
void split2_kernel(const float* __restrict__ src, __half* __restrict__ dst,
                   int K, int isA)
{
    int idx = blockIdx.x * blockDim.x + threadIdx.x;
    int k4cnt = K >> 2;
    int r  = idx / k4cnt;
    int k  = (idx - r * k4cnt) << 2;

    float4 v = *(const float4*)&src[(size_t)r * K + k];
    __half h0 = __float2half(v.x), h1 = __float2half(v.y);
    __half h2 = __float2half(v.z), h3 = __float2half(v.w);
    __half l0 = __float2half(v.x - __half2float(h0));
    __half l1 = __float2half(v.y - __half2float(h1));
    __half l2 = __float2half(v.z - __half2float(h2));
    __half l3 = __float2half(v.w - __half2float(h3));

    union { __half b[4]; uint2 u; } hi, lo;
    hi.b[0]=h0; hi.b[1]=h1; hi.b[2]=h2; hi.b[3]=h3;
    lo.b[0]=l0; lo.b[1]=l1; lo.b[2]=l2; lo.b[3]=l3;

    size_t base = (size_t)r * (2 * K) + k;
    *(uint2*)&dst[base]     = hi.u;
    *(uint2*)&dst[base + K] = isA ? lo.u : hi.u;
}

// ---------------------------------------------------------------------------
// mma.sync fp16 GEMM: C[M, ldc](fp32) = A2[M, K2] @ B2[N, K2]^T
// Tile 128x128x64, 256 threads (8 warps, 2x4), warp tile 64x32.
// 3-stage cp.async circular pipeline (110.6 KB dynamic smem), 2 CTAs/SM.
// ---------------------------------------------------------------------------
#define BK 64
#define ASTR 72
#define NIT (K2 / BK)                  // 64
#define STAGES 3
#define MAT_ELEMS (128 * ASTR)
#define STAGE_ELEMS (2 * MAT_ELEMS)
#define GEMM_SMEM (STAGES * STAGE_ELEMS * 2)

__global__ __launch_bounds__(256, 2)
void gemm_mma_kernel(const __half* __restrict__ A2,
                     const __half* __restrict__ B2,
                     float* __restrict__ C, int ldc)
{
    extern __shared__ __half smem[];

    const int tid  = threadIdx.x;
    const int wid  = tid >> 5;
    const int lane = tid & 31;
    const int warp_m = wid & 1;
    const int warp_n = wid >> 1;
    const int m0 = blockIdx.y * 128;
    const int n0 = blockIdx.x * 128;

    const __half* Abase = A2 + (size_t)m0 * K2;
    const __half* Bbase = B2 + (size_t)n0 * K2;

    const uint32_t smem_u32 = (uint32_t)__cvta_generic_to_shared(smem);

    int rowL[8], segL[8], isBL[8];
    uint32_t soff[8];
    #pragma unroll
    for (int r = 0; r < 8; r++) {
        int chunk = tid + r * 256;
        isBL[r] = chunk >> 10;
        int cc  = chunk & 1023;
        rowL[r] = cc >> 3;
        segL[r] = cc & 7;
        soff[r] = isBL[r] * MAT_ELEMS + rowL[r] * ASTR + segL[r] * 8;
    }

    auto load_tile = [&](int it, int st) {
        int k0 = it * BK;
        uint32_t sbase = smem_u32 + (uint32_t)(st * STAGE_ELEMS) * 2;
        #pragma unroll
        for (int r = 0; r < 8; r++) {
            const __half* src =
                (isBL[r] ? Bbase : Abase) + (size_t)rowL[r] * K2 + k0 + segL[r] * 8;
            CP_ASYNC16(sbase + soff[r] * 2, src);
        }
    };

    float d[4][4][4];
    #pragma unroll
    for (int i = 0; i < 4; i++)
        #pragma unroll
        for (int j = 0; j < 4; j++)
            #pragma unroll
            for (int q = 0; q < 4; q++) d[i][j][q] = 0.f;

    load_tile(0, 0); CP_COMMIT();
    load_tile(1, 1); CP_COMMIT();

    const int lrow = lane & 15;
    const int lcol = (lane >> 4) << 3;

    int cur = 0, pf = 2;
    for (int it = 0; it < NIT; it++) {
        CP_WAIT(1);
        __syncthreads();

        if (it + 2 < NIT) load_tile(it + 2, pf);
        CP_COMMIT();

        const __half* As = smem + cur * STAGE_ELEMS;
        const __half* Bs = As + MAT_ELEMS;

        #pragma unroll
        for (int ks = 0; ks < BK; ks += 16) {
            uint32_t a[4][4], b[2][4];
            #pragma unroll
            for (int i = 0; i < 4; i++) {
                uint32_t addr = (uint32_t)__cvta_generic_to_shared(
                    As + (warp_m * 64 + i * 16 + lrow) * ASTR + ks + lcol);
                LDSM4(a[i][0], a[i][1], a[i][2], a[i][3], addr);
            }
            #pragma unroll
            for (int j = 0; j < 2; j++) {
                uint32_t addr = (uint32_t)__cvta_generic_to_shared(
                    Bs + (warp_n * 32 + j * 16 + lrow) * ASTR + ks + lcol);
                LDSM4(b[j][0], b[j][1], b[j][2], b[j][3], addr);
            }
            #pragma unroll
            for (int i = 0; i < 4; i++) {
                #pragma unroll
                for (int jj = 0; jj < 4; jj++) {
                    uint32_t b0 = b[jj >> 1][(jj & 1)];
                    uint32_t b1 = b[jj >> 1][(jj & 1) + 2];
                    MMAF16(d[i][jj][0], d[i][jj][1], d[i][jj][2], d[i][jj][3],
                           a[i][0], a[i][1], a[i][2], a[i][3], b0, b1);
                }
            }
        }

        cur = (cur == 2) ? 0 : cur + 1;
        pf  = (pf  == 2) ? 0 : pf  + 1;
    }

    const int crow = lane >> 2;
    const int ccol = (lane & 3) * 2;
    #pragma unroll
    for (int i = 0; i < 4; i++) {
        #pragma unroll
        for (int jj = 0; jj < 4; jj++) {
            int m = m0 + warp_m * 64 + i * 16 + crow;
            int n = n0 + warp_n * 32 + jj * 8 + ccol;
            *(float2*)&C[(size_t)m * ldc + n] =
                make_float2(d[i][jj][0], d[i][jj][1]);
            *(float2*)&C[(size_t)(m + 8) * ldc + n] =
                make_float2(d[i][jj][2], d[i][jj][3]);
        }
    }
}

// ---------------------------------------------------------------------------
// prep: RoPE q,k -> fp16 2-term split [hi|lo]; V -> fp16 transposed [hd][t].
// ---------------------------------------------------------------------------
__global__ __launch_bounds__(256)
void prep_kernel(const float* __restrict__ qkv, const float* __restrict__ freqs,
                 __half* __restrict__ q2, __half* __restrict__ k2,
                 __half* __restrict__ vt)
{
    __shared__ float sv[64 * 128];
    const int tt = blockIdx.x, h = blockIdx.y, b = blockIdx.z;
    const int tid = threadIdx.x;
    const size_t bh = (size_t)b * NH + h;

    for (int i = tid; i < 64 * 32; i += 256) {
        int r = i >> 5, c4 = (i & 31) * 4;
        *(float4*)&sv[r * 128 + c4] =
            *(const float4*)&qkv[(size_t)(b * SEQ + tt * 64 + r) * QKV_N + 2 * DIM + h * HD + c4];
    }

    for (int i = tid; i < 64 * 64; i += 256) {
        int r = i >> 6, j = i & 63;
        int t = tt * 64 + r;
        size_t base = (size_t)(b * SEQ + t) * QKV_N + h * HD + 2 * j;
        float q0 = qkv[base],        q1 = qkv[base + 1];
        float k0 = qkv[base + DIM],  k1 = qkv[base + DIM + 1];
        float ang = freqs[t * HD + 2 * j];
        float c = cosf(ang), s = sinf(ang);
        float qr0 = q0 * c - q1 * s, qr1 = q1 * c + q0 * s;
        float kr0 = k0 * c - k1 * s, kr1 = k1 * c + k0 * s;

        union { __half h[2]; uint32_t u; } p;
        size_t row = (bh * SEQ + t) * 256;

        __half qh0 = __float2half(qr0), qh1 = __float2half(qr1);
        p.h[0] = qh0; p.h[1] = qh1;                     *(uint32_t*)&q2[row + 2*j] = p.u;
        p.h[0] = __float2half(qr0 - __half2float(qh0));
        p.h[1] = __float2half(qr1 - __half2float(qh1)); *(uint32_t*)&q2[row + 128 + 2*j] = p.u;

        __half kh0 = __float2half(kr0), kh1 = __float2half(kr1);
        p.h[0] = kh0; p.h[1] = kh1;                     *(uint32_t*)&k2[row + 2*j] = p.u;
        p.h[0] = __float2half(kr0 - __half2float(kh0));
        p.h[1] = __float2half(kr1 - __half2float(kh1)); *(uint32_t*)&k2[row + 128 + 2*j] = p.u;
    }
    __syncthreads();

    for (int i = tid; i < 128 * 32; i += 256) {
        int hd = i >> 5, c = i & 31;
        union { __half h[2]; uint32_t u; } p;
        p.h[0] = __float2half(sv[(2 * c)     * 128 + hd]);
        p.h[1] = __float2half(sv[(2 * c + 1) * 128 + hd]);
        *(uint32_t*)&vt[(bh * 128 + hd) * SEQ + tt * 64 + 2 * c] = p.u;
    }
}

// ---------------------------------------------------------------------------
// Tensor-core causal flash attention (fp16 HMMA), R14-proven structure.
// Epilogue now writes fp16 2-block split [hi | lo] into g_attn2 (stride 2*DIM).
// ---------------------------------------------------------------------------
#define AQ_STR 264
#define AV_STR 72
#define Q2_ELEM (128 * AQ_STR)
#define K2_ELEM (64 * AQ_STR)
#define VT_ELEM (128 * AV_STR)
#define ATTN_SMEM ((Q2_ELEM + 2 * K2_ELEM + 2 * VT_ELEM) * 2)   // 172032 B

__global__ __launch_bounds__(256)
void attn_tc_kernel(const __half* __restrict__ q2, const __half* __restrict__ k2,
                    const __half* __restrict__ vt, __half* __restrict__ attn2)
{
    const float scale = 0.08838834764831843f;

    extern __shared__ __half sh[];
    __half* Qs  = sh;
    __half* Kst = Qs + Q2_ELEM;
    __half* Vst = Kst + 2 * K2_ELEM;

    const int qt   = gridDim.x - 1 - blockIdx.x;
    const int head = blockIdx.y;
    const int b    = blockIdx.z;
    const int tid  = threadIdx.x;
    const int w    = tid >> 5;
    const int lane = tid & 31;
    const int r0   = lane >> 2;
    const int c0   = (lane & 3) * 2;
    const size_t bh = (size_t)b * NH + head;

    const uint32_t sbase = (uint32_t)__cvta_generic_to_shared(sh);
    const uint32_t qs_u  = sbase;
    const uint32_t ks_u  = sbase + Q2_ELEM * 2;
    const uint32_t vs_u  = ks_u + 2 * K2_ELEM * 2;

    auto loadQ = [&]() {
        #pragma unroll
        for (int i = 0; i < 16; i++) {
            int ch = tid + i * 256;
            int row = ch >> 5, seg = ch & 31;
            const __half* src = q2 + (bh * SEQ + qt * 128 + row) * 256 + seg * 8;
            CP_ASYNC16(qs_u + (uint32_t)(row * AQ_STR + seg * 8) * 2, src);
        }
    };
    auto loadKV = [&](int kt, int buf) {
        uint32_t kb = ks_u + (uint32_t)(buf * K2_ELEM) * 2;
        #pragma unroll
        for (int i = 0; i < 8; i++) {
            int ch = tid + i * 256;
            int row = ch >> 5, seg = ch & 31;
            const __half* src = k2 + (bh * SEQ + kt * 64 + row) * 256 + seg * 8;
            CP_ASYNC16(kb + (uint32_t)(row * AQ_STR + seg * 8) * 2, src);
        }
        uint32_t vb = vs_u + (uint32_t)(buf * VT_ELEM) * 2;
        #pragma unroll
        for (int i = 0; i < 4; i++) {
            int ch = tid + i * 256;
            int row = ch >> 3, seg = ch & 7;
            const __half* src = vt + (bh * 128 + row) * SEQ + kt * 64 + seg * 8;
            CP_ASYNC16(vb + (uint32_t)(row * AV_STR + seg * 8) * 2, src);
        }
    };

    loadQ();
    loadKV(0, 0);
    CP_COMMIT();

    float o[16][4];
    #pragma unroll
    for (int j = 0; j < 16; j++)
        #pragma unroll
        for (int q = 0; q < 4; q++) o[j][q] = 0.f;
    float m_i[2] = { -INFINITY, -INFINITY };
    float l_i[2] = { 0.f, 0.f };

    const int grow0 = qt * 128 + w * 16 + r0;
    const int grow1 = grow0 + 8;
    const int ktmax = 2 * qt + 1;

    for (int kt = 0; kt <= ktmax; kt++) {
        const int cur = kt & 1;
        CP_WAIT(0);
        __syncthreads();
        if (kt < ktmax) { loadKV(kt + 1, cur ^ 1); CP_COMMIT(); }

        const __half* Ks = Kst + cur * K2_ELEM;
        const __half* Vs = Vst + cur * VT_ELEM;

        float s[8][4];
        #pragma unroll
        for (int jn = 0; jn < 8; jn++)
            #pragma unroll
            for (int q = 0; q < 4; q++) s[jn][q] = 0.f;

        #pragma unroll
        for (int j = 0; j < 24; j++) {
            const int qoff = (j < 16) ? (j & 7) * 16 : 128 + (j - 16) * 16;
            const int koff = (j < 8) ? j * 16 : ((j < 16) ? 128 + (j - 8) * 16 : (j - 16) * 16);
            const __half* qa = Qs + (w * 16 + r0) * AQ_STR + qoff + c0;
            uint32_t a0 = *(const uint32_t*)qa;
            uint32_t a1 = *(const uint32_t*)(qa + 8 * AQ_STR);
            uint32_t a2 = *(const uint32_t*)(qa + 8);
            uint32_t a3 = *(const uint32_t*)(qa + 8 * AQ_STR + 8);
            #pragma unroll
            for (int jn = 0; jn < 8; jn++) {
                const __half* kb = Ks + (jn * 8 + r0) * AQ_STR + koff + c0;
                uint32_t b0 = *(const uint32_t*)kb;
                uint32_t b1 = *(const uint32_t*)(kb + 8);
                MMAF16(s[jn][0], s[jn][1], s[jn][2], s[jn][3], a0, a1, a2, a3, b0, b1);
            }
        }

        float rm0 = -INFINITY, rm1 = -INFINITY;
        #pragma unroll
        for (int jn = 0; jn < 8; jn++) {
            int gcol = kt * 64 + jn * 8 + c0;
            s[jn][0] = (gcol     > grow0) ? -INFINITY : s[jn][0] * scale;
            s[jn][1] = (gcol + 1 > grow0) ? -INFINITY : s[jn][1] * scale;
            s[jn][2] = (gcol     > grow1) ? -INFINITY : s[jn][2] * scale;
            s[jn][3] = (gcol + 1 > grow1) ? -INFINITY : s[jn][3] * scale;
            rm0 = fmaxf(rm0, fmaxf(s[jn][0], s[jn][1]));
            rm1 = fmaxf(rm1, fmaxf(s[jn][2], s[jn][3]));
        }
        rm0 = fmaxf(rm0, __shfl_xor_sync(0xffffffffu, rm0, 1));
        rm0 = fmaxf(rm0, __shfl_xor_sync(0xffffffffu, rm0, 2));
        rm1 = fmaxf(rm1, __shfl_xor_sync(0xffffffffu, rm1, 1));
        rm1 = fmaxf(rm1, __shfl_xor_sync(0xffffffffu, rm1, 2));

        float mn0 = fmaxf(m_i[0], rm0), mn1 = fmaxf(m_i[1], rm1);
        float f0 = __expf(m_i[0] - mn0), f1 = __expf(m_i[1] - mn1);
        float ps0 = 0.f, ps1 = 0.f;
        #pragma unroll
        for (int jn = 0; jn < 8; jn++) {
            s[jn][0] = __expf(s[jn][0] - mn0);
            s[jn][1] = __expf(s[jn][1] - mn0);
            s[jn][2] = __expf(s[jn][2] - mn1);
            s[jn][3] = __expf(s[jn][3] - mn1);
            ps0 += s[jn][0] + s[jn][1];
            ps1 += s[jn][2] + s[jn][3];
        }
        ps0 += __shfl_xor_sync(0xffffffffu, ps0, 1);
        ps0 += __shfl_xor_sync(0xffffffffu, ps0, 2);
        ps1 += __shfl_xor_sync(0xffffffffu, ps1, 1);
        ps1 += __shfl_xor_sync(0xffffffffu, ps1, 2);
        l_i[0] = l_i[0] * f0 + ps0;  m_i[0] = mn0;
        l_i[1] = l_i[1] * f1 + ps1;  m_i[1] = mn1;
        #pragma unroll
        for (int j = 0; j < 16; j++) {
            o[j][0] *= f0; o[j][1] *= f0; o[j][2] *= f1; o[j][3] *= f1;
        }

        #pragma unroll
        for (int kt2 = 0; kt2 < 4; kt2++) {
            union { __half2 h; uint32_t u; } pa0, pa1, pa2, pa3;
            pa0.h = __floats2half2_rn(s[2*kt2][0],     s[2*kt2][1]);
            pa1.h = __floats2half2_rn(s[2*kt2][2],     s[2*kt2][3]);
            pa2.h = __floats2half2_rn(s[2*kt2 + 1][0], s[2*kt2 + 1][1]);
            pa3.h = __floats2half2_rn(s[2*kt2 + 1][2], s[2*kt2 + 1][3]);
            #pragma unroll
            for (int jn2 = 0; jn2 < 16; jn2++) {
                const __half* vb = Vs + (jn2 * 8 + r0) * AV_STR + kt2 * 16 + c0;
                uint32_t b0 = *(const uint32_t*)vb;
                uint32_t b1 = *(const uint32_t*)(vb + 8);
                MMAF16(o[jn2][0], o[jn2][1], o[jn2][2], o[jn2][3],
                       pa0.u, pa1.u, pa2.u, pa3.u, b0, b1);
            }
        }
    }

    // ---- epilogue: normalize + fp16 2-block split [hi | lo] (stride 2*DIM) ----
    float inv0 = 1.f / l_i[0], inv1 = 1.f / l_i[1];
    size_t row0 = (size_t)(b * SEQ + grow0);
    size_t row1 = (size_t)(b * SEQ + grow1);
    #pragma unroll
    for (int jn2 = 0; jn2 < 16; jn2++) {
        int hd = head * HD + jn2 * 8 + c0;
        float v00 = o[jn2][0] * inv0, v01 = o[jn2][1] * inv0;
        float v10 = o[jn2][2] * inv1, v11 = o[jn2][3] * inv1;

        union { __half b[2]; uint32_t u; } hi, lo;
        __half h0, h1;

        h0 = __float2half(v00); h1 = __float2half(v01);
        hi.b[0] = h0; hi.b[1] = h1;
        lo.b[0] = __float2half(v00 - __half2float(h0));
        lo.b[1] = __float2half(v01 - __half2float(h1));
        size_t base0 = row0 * (2 * DIM) + hd;
        *(uint32_t*)&attn2[base0]       = hi.u;
        *(uint32_t*)&attn2[base0 + DIM] = lo.u;

        h0 = __float2half(v10); h1 = __float2half(v11);
        hi.b[0] = h0; hi.b[1] = h1;
        lo.b[0] = __float2half(v10 - __half2float(h0));
        lo.b[1] = __float2half(v11 - __half2float(h1));
        size_t base1 = row1 * (2 * DIM) + hd;
        *(uint32_t*)&attn2[base1]       = hi.u;
        *(uint32_t*)&attn2[base1 + DIM] = lo.u;
    }
}

// ---------------------------------------------------------------------------
// launcher
// ---------------------------------------------------------------------------
extern "C" void kernel_launch(void* const* d_in, const int* in_sizes, int n_in,
                              void* d_out, int out_size)
{
    const float* x     = (const float*)d_in[0];
    const float* freqs = (const float*)d_in[1];
    const float* Wqkv  = (const float*)d_in[2];
    const float* Wout  = (const float*)d_in[3];
    float* out = (float*)d_out;

    float *qkv;
    __half *x2, *wqkv2, *attn2, *wout2, *q2, *k2, *vt;
    cudaGetSymbolAddress((void**)&qkv,   g_qkv);
    cudaGetSymbolAddress((void**)&x2,    g_x2);
    cudaGetSymbolAddress((void**)&wqkv2, g_wqkv2);
    cudaGetSymbolAddress((void**)&attn2, g_attn2);
    cudaGetSymbolAddress((void**)&wout2, g_wout2);
    cudaGetSymbolAddress((void**)&q2,    g_q2);
    cudaGetSymbolAddress((void**)&k2,    g_k2);
    cudaGetSymbolAddress((void**)&vt,    g_vt);

    cudaFuncSetAttribute(gemm_mma_kernel,
                         cudaFuncAttributeMaxDynamicSharedMemorySize, GEMM_SMEM);
    cudaFuncSetAttribute(attn_tc_kernel,
                         cudaFuncAttributeMaxDynamicSharedMemorySize, ATTN_SMEM);

    // 1) fp16 2-split conversions for stage-1 GEMM
    split2_kernel<<<(M_TOT * (DIM/4)) / 256, 256>>>(x,    x2,    DIM, 1);
    split2_kernel<<<(QKV_N * (DIM/4)) / 256, 256>>>(Wqkv, wqkv2, DIM, 0);

    // 2) QKV projection (fp16 tensor cores, K'=4096)
    gemm_mma_kernel<<<dim3(QKV_N/128, M_TOT/128), 256, GEMM_SMEM>>>(x2, wqkv2, qkv, QKV_N);

    // 3) prep: rope -> fp16 split q2/k2, transposed fp16 V
    prep_kernel<<<dim3(SEQ/64, NH, BATCH), 256>>>(qkv, freqs, q2, k2, vt);

    // 4) tensor-core causal flash attention -> g_attn2 (fp16 2-split)
    attn_tc_kernel<<<dim3(SEQ/128, NH, BATCH), 256, ATTN_SMEM>>>(q2, k2, vt, attn2);

    // 5) weight conversion for stage-2 GEMM
    split2_kernel<<<(DIM * (DIM/4)) / 256, 256>>>(Wout, wout2, DIM, 0);

    // 6) output projection (fp16 tensor cores)
    gemm_mma_kernel<<<dim3(DIM/128, M_TOT/128), 256, GEMM_SMEM>>>(attn2, wout2, out, DIM);
}

// round 16
// speedup vs baseline: 2.1892x; 1.0321x over previous
#include <cuda_runtime.h>
#include <cuda_bf16.h>
#include <cuda_fp16.h>
#include <math.h>
#include <stdint.h>

// Problem constants
#define BATCH 2
#define SEQ   2048
#define DIM   2048
#define NH    16
#define HD    128
#define M_TOT (BATCH*SEQ)      // 4096
#define QKV_N (3*DIM)          // 6144
#define K2    (2*DIM)          // fp16 2-term split K = 4096

// ---------------------------------------------------------------------------
// Scratch (allocation-free rule: __device__ globals)
// ---------------------------------------------------------------------------
__device__ __half g_x2   [M_TOT * K2];            // 33.5 MB  [hi|lo]
__device__ __half g_wqkv1[QKV_N * DIM];           // 25 MB    hi only
__device__ __half g_attn2[M_TOT * K2];            // 33.5 MB  [hi|lo] (from attention)
__device__ __half g_wout1[DIM   * DIM];           // 8.4 MB   hi only
__device__ __half g_q2[BATCH * NH * SEQ * 256];   // 33.5 MB  [qh(128)|ql(128)]
__device__ __half g_k2[BATCH * NH * SEQ * 256];   // 33.5 MB  [kh(128)|kl(128)]
__device__ __half g_vt[BATCH * NH * HD * SEQ];    // 16.8 MB  transposed [hd][t]

// ---------------------------------------------------------------------------
// mma.sync / ldmatrix / cp.async helpers (baseline sm_80+ PTX, works on sm_100)
// ---------------------------------------------------------------------------
#define LDSM4(r0, r1, r2, r3, addr) \
    asm volatile("ldmatrix.sync.aligned.m8n8.x4.shared.b16 {%0,%1,%2,%3}, [%4];" \
                 : "=r"(r0), "=r"(r1), "=r"(r2), "=r"(r3) : "r"(addr))

#define MMAF16(d0, d1, d2, d3, a0, a1, a2, a3, b0, b1) \
    asm volatile("mma.sync.aligned.m16n8k16.row.col.f32.f16.f16.f32 " \
                 "{%0,%1,%2,%3}, {%4,%5,%6,%7}, {%8,%9}, {%0,%1,%2,%3};" \
                 : "+f"(d0), "+f"(d1), "+f"(d2), "+f"(d3) \
                 : "r"(a0), "r"(a1), "r"(a2), "r"(a3), "r"(b0), "r"(b1))

#define CP_ASYNC16(dst_u32, src) \
    asm volatile("cp.async.cg.shared.global [%0], [%1], 16;" :: "r"(dst_u32), "l"(src))
#define CP_COMMIT() asm volatile("cp.async.commit_group;" ::: "memory")
#define CP_WAIT(n)  asm volatile("cp.async.wait_group %0;" :: "n"(n) : "memory")

// ---------------------------------------------------------------------------
// split2: fp32 -> 2-block fp16 split along K (A operands): [hi | lo]
// ---------------------------------------------------------------------------
__global__ __launch_bounds__(256)
void split2_kernel(const float* __restrict__ src, __half* __restrict__ dst, int K)
{
    int idx = blockIdx.x * blockDim.x + threadIdx.x;
    int k4cnt = K >> 2;
    int r  = idx / k4cnt;
    int k  = (idx - r * k4cnt) << 2;

    float4 v = *(const float4*)&src[(size_t)r * K + k];
    __half h0 = __float2half(v.x), h1 = __float2half(v.y);
    __half h2 = __float2half(v.z), h3 = __float2half(v.w);

    union { __half b[4]; uint2 u; } hi, lo;
    hi.b[0]=h0; hi.b[1]=h1; hi.b[2]=h2; hi.b[3]=h3;
    lo.b[0]=__float2half(v.x - __half2float(h0));
    lo.b[1]=__float2half(v.y - __half2float(h1));
    lo.b[2]=__float2half(v.z - __half2float(h2));
    lo.b[3]=__float2half(v.w - __half2float(h3));

    size_t base = (size_t)r * (2 * K) + k;
    *(uint2*)&dst[base]     = hi.u;
    *(uint2*)&dst[base + K] = lo.u;
}

// split1: fp32 -> fp16 hi only (B operands, dedup'd), stride K
__global__ __launch_bounds__(256)
void split1_kernel(const float* __restrict__ src, __half* __restrict__ dst, int K)
{
    int idx = blockIdx.x * blockDim.x + threadIdx.x;
    int k4cnt = K >> 2;
    int r  = idx / k4cnt;
    int k  = (idx - r * k4cnt) << 2;

    float4 v = *(const float4*)&src[(size_t)r * K + k];
    union { __half b[4]; uint2 u; } hi;
    hi.b[0]=__float2half(v.x); hi.b[1]=__float2half(v.y);
    hi.b[2]=__float2half(v.z); hi.b[3]=__float2half(v.w);
    *(uint2*)&dst[(size_t)r * K + k] = hi.u;
}

// ---------------------------------------------------------------------------
// mma.sync fp16 GEMM: C = A2[M, K2] @ B1[N, K]^T  (B hi block dedup'd: the
// logical [hi|hi] layout is folded via bk0 = k0 & (DIM-1)).
// Tile 128x128x64, 256 threads, 3-stage cp.async, 2 CTAs/SM.
// mode 0: fp32 C store (ldc).  mode 1: fused RoPE + fp16-split epilogue
// writing q2/k2 ([hi|lo], 256/row) and vt (transposed fp16).
// ---------------------------------------------------------------------------
#define BK 64
#define ASTR 72
#define NIT (K2 / BK)                  // 64
#define MAT_ELEMS (128 * ASTR)
#define STAGE_ELEMS (2 * MAT_ELEMS)
#define GEMM_SMEM (3 * STAGE_ELEMS * 2)

__global__ __launch_bounds__(256, 2)
void gemm_mma_kernel(const __half* __restrict__ A2,
                     const __half* __restrict__ B1,
                     float* __restrict__ C, int ldc, int mode,
                     const float* __restrict__ freqs,
                     __half* __restrict__ q2, __half* __restrict__ k2,
                     __half* __restrict__ vt)
{
    extern __shared__ __half smem[];

    const int tid  = threadIdx.x;
    const int wid  = tid >> 5;
    const int lane = tid & 31;
    const int warp_m = wid & 1;
    const int warp_n = wid >> 1;
    const int m0 = blockIdx.y * 128;
    const int n0 = blockIdx.x * 128;

    const __half* Abase = A2 + (size_t)m0 * K2;
    const __half* Bbase = B1 + (size_t)n0 * DIM;

    const uint32_t smem_u32 = (uint32_t)__cvta_generic_to_shared(smem);

    int rowL[8], segL[8], isBL[8];
    uint32_t soff[8];
    #pragma unroll
    for (int r = 0; r < 8; r++) {
        int chunk = tid + r * 256;
        isBL[r] = chunk >> 10;
        int cc  = chunk & 1023;
        rowL[r] = cc >> 3;
        segL[r] = cc & 7;
        soff[r] = isBL[r] * MAT_ELEMS + rowL[r] * ASTR + segL[r] * 8;
    }

    auto load_tile = [&](int it, int st) {
        int k0 = it * BK;
        int bk0 = k0 & (DIM - 1);       // B hi block dedup
        uint32_t sbase = smem_u32 + (uint32_t)(st * STAGE_ELEMS) * 2;
        #pragma unroll
        for (int r = 0; r < 8; r++) {
            const __half* src = isBL[r]
                ? Bbase + (size_t)rowL[r] * DIM + bk0 + segL[r] * 8
                : Abase + (size_t)rowL[r] * K2  + k0  + segL[r] * 8;
            CP_ASYNC16(sbase + soff[r] * 2, src);
        }
    };

    float d[4][4][4];
    #pragma unroll
    for (int i = 0; i < 4; i++)
        #pragma unroll
        for (int j = 0; j < 4; j++)
            #pragma unroll
            for (int q = 0; q < 4; q++) d[i][j][q] = 0.f;

    load_tile(0, 0); CP_COMMIT();
    load_tile(1, 1); CP_COMMIT();

    const int lrow = lane & 15;
    const int lcol = (lane >> 4) << 3;

    int cur = 0, pf = 2;
    for (int it = 0; it < NIT; it++) {
        CP_WAIT(1);
        __syncthreads();

        if (it + 2 < NIT) load_tile(it + 2, pf);
        CP_COMMIT();

        const __half* As = smem + cur * STAGE_ELEMS;
        const __half* Bs = As + MAT_ELEMS;

        #pragma unroll
        for (int ks = 0; ks < BK; ks += 16) {
            uint32_t a[4][4], b[2][4];
            #pragma unroll
            for (int i = 0; i < 4; i++) {
                uint32_t addr = (uint32_t)__cvta_generic_to_shared(
                    As + (warp_m * 64 + i * 16 + lrow) * ASTR + ks + lcol);
                LDSM4(a[i][0], a[i][1], a[i][2], a[i][3], addr);
            }
            #pragma unroll
            for (int j = 0; j < 2; j++) {
                uint32_t addr = (uint32_t)__cvta_generic_to_shared(
                    Bs + (warp_n * 32 + j * 16 + lrow) * ASTR + ks + lcol);
                LDSM4(b[j][0], b[j][1], b[j][2], b[j][3], addr);
            }
            #pragma unroll
            for (int i = 0; i < 4; i++) {
                #pragma unroll
                for (int jj = 0; jj < 4; jj++) {
                    uint32_t b0 = b[jj >> 1][(jj & 1)];
                    uint32_t b1 = b[jj >> 1][(jj & 1) + 2];
                    MMAF16(d[i][jj][0], d[i][jj][1], d[i][jj][2], d[i][jj][3],
                           a[i][0], a[i][1], a[i][2], a[i][3], b0, b1);
                }
            }
        }

        cur = (cur == 2) ? 0 : cur + 1;
        pf  = (pf  == 2) ? 0 : pf  + 1;
    }

    const int crow = lane >> 2;
    const int ccol = (lane & 3) * 2;

    if (mode == 0) {
        #pragma unroll
        for (int i = 0; i < 4; i++) {
            #pragma unroll
            for (int jj = 0; jj < 4; jj++) {
                int m = m0 + warp_m * 64 + i * 16 + crow;
                int n = n0 + warp_n * 32 + jj * 8 + ccol;
                *(float2*)&C[(size_t)m * ldc + n] =
                    make_float2(d[i][jj][0], d[i][jj][1]);
                *(float2*)&C[(size_t)(m + 8) * ldc + n] =
                    make_float2(d[i][jj][2], d[i][jj][3]);
            }
        }
        return;
    }

    // ---- mode 1: fused RoPE + fp16 split epilogue ----
    #pragma unroll
    for (int i = 0; i < 4; i++) {
        #pragma unroll
        for (int jj = 0; jj < 4; jj++) {
            int m = m0 + warp_m * 64 + i * 16 + crow;
            int n = n0 + warp_n * 32 + jj * 8 + ccol;
            int sec  = n >> 11;            // 0=q, 1=k, 2=v
            int head = (n >> 7) & 15;
            int hd   = n & 127;            // even
            int b    = m >> 11;
            int t0   = m & 2047;
            size_t bh = (size_t)b * NH + head;

            float d0 = d[i][jj][0], d1 = d[i][jj][1];
            float d2 = d[i][jj][2], d3 = d[i][jj][3];

            if (sec == 2) {
                __half* vp0 = vt + (bh * 128 + hd)     * SEQ;
                __half* vp1 = vt + (bh * 128 + hd + 1) * SEQ;
                vp0[t0]     = __float2half(d0);
                vp1[t0]     = __float2half(d1);
                vp0[t0 + 8] = __float2half(d2);
                vp1[t0 + 8] = __float2half(d3);
            } else {
                float ang0 = freqs[t0 * HD + hd];
                float ang8 = freqs[(t0 + 8) * HD + hd];
                float c0r = cosf(ang0), s0r = sinf(ang0);
                float c8r = cosf(ang8), s8r = sinf(ang8);
                float r0 = d0 * c0r - d1 * s0r, r1 = d1 * c0r + d0 * s0r;
                float r2 = d2 * c8r - d3 * s8r, r3 = d3 * c8r + d2 * s8r;

                __half* dst = (sec == 0) ? q2 : k2;
                size_t row  = (bh * SEQ + t0) * 256;
                size_t row8 = row + 8 * 256;
                union { __half h[2]; uint32_t u; } p;
                __half h0, h1;

                h0 = __float2half(r0); h1 = __float2half(r1);
                p.h[0] = h0; p.h[1] = h1;              *(uint32_t*)&dst[row + hd] = p.u;
                p.h[0] = __float2half(r0 - __half2float(h0));
                p.h[1] = __float2half(r1 - __half2float(h1));
                *(uint32_t*)&dst[row + 128 + hd] = p.u;

                h0 = __float2half(r2); h1 = __float2half(r3);
                p.h[0] = h0; p.h[1] = h1;              *(uint32_t*)&dst[row8 + hd] = p.u;
                p.h[0] = __float2half(r2 - __half2float(h0));
                p.h[1] = __float2half(r3 - __half2float(h1));
                *(uint32_t*)&dst[row8 + 128 + hd] = p.u;
            }
        }
    }
}

// ---------------------------------------------------------------------------
// Tensor-core causal flash attention (fp16 HMMA), unchanged from R15.
// Epilogue writes fp16 2-block split [hi | lo] into g_attn2 (stride 2*DIM).
// ---------------------------------------------------------------------------
#define AQ_STR 264
#define AV_STR 72
#define Q2_ELEM (128 * AQ_STR)
#define K2_ELEM (64 * AQ_STR)
#define VT_ELEM (128 * AV_STR)
#define ATTN_SMEM ((Q2_ELEM + 2 * K2_ELEM + 2 * VT_ELEM) * 2)   // 172032 B

__global__ __launch_bounds__(256)
void attn_tc_kernel(const __half* __restrict__ q2, const __half* __restrict__ k2,
                    const __half* __restrict__ vt, __half* __restrict__ attn2)
{
    const float scale = 0.08838834764831843f;

    extern __shared__ __half sh[];
    __half* Qs  = sh;
    __half* Kst = Qs + Q2_ELEM;
    __half* Vst = Kst + 2 * K2_ELEM;

    const int qt   = gridDim.x - 1 - blockIdx.x;
    const int head = blockIdx.y;
    const int b    = blockIdx.z;
    const int tid  = threadIdx.x;
    const int w    = tid >> 5;
    const int lane = tid & 31;
    const int r0   = lane >> 2;
    const int c0   = (lane & 3) * 2;
    const size_t bh = (size_t)b * NH + head;

    const uint32_t sbase = (uint32_t)__cvta_generic_to_shared(sh);
    const uint32_t qs_u  = sbase;
    const uint32_t ks_u  = sbase + Q2_ELEM * 2;
    const uint32_t vs_u  = ks_u + 2 * K2_ELEM * 2;

    auto loadQ = [&]() {
        #pragma unroll
        for (int i = 0; i < 16; i++) {
            int ch = tid + i * 256;
            int row = ch >> 5, seg = ch & 31;
            const __half* src = q2 + (bh * SEQ + qt * 128 + row) * 256 + seg * 8;
            CP_ASYNC16(qs_u + (uint32_t)(row * AQ_STR + seg * 8) * 2, src);
        }
    };
    auto loadKV = [&](int kt, int buf) {
        uint32_t kb = ks_u + (uint32_t)(buf * K2_ELEM) * 2;
        #pragma unroll
        for (int i = 0; i < 8; i++) {
            int ch = tid + i * 256;
            int row = ch >> 5, seg = ch & 31;
            const __half* src = k2 + (bh * SEQ + kt * 64 + row) * 256 + seg * 8;
            CP_ASYNC16(kb + (uint32_t)(row * AQ_STR + seg * 8) * 2, src);
        }
        uint32_t vb = vs_u + (uint32_t)(buf * VT_ELEM) * 2;
        #pragma unroll
        for (int i = 0; i < 4; i++) {
            int ch = tid + i * 256;
            int row = ch >> 3, seg = ch & 7;
            const __half* src = vt + (bh * 128 + row) * SEQ + kt * 64 + seg * 8;
            CP_ASYNC16(vb + (uint32_t)(row * AV_STR + seg * 8) * 2, src);
        }
    };

    loadQ();
    loadKV(0, 0);
    CP_COMMIT();

    float o[16][4];
    #pragma unroll
    for (int j = 0; j < 16; j++)
        #pragma unroll
        for (int q = 0; q < 4; q++) o[j][q] = 0.f;
    float m_i[2] = { -INFINITY, -INFINITY };
    float l_i[2] = { 0.f, 0.f };

    const int grow0 = qt * 128 + w * 16 + r0;
    const int grow1 = grow0 + 8;
    const int ktmax = 2 * qt + 1;

    for (int kt = 0; kt <= ktmax; kt++) {
        const int cur = kt & 1;
        CP_WAIT(0);
        __syncthreads();
        if (kt < ktmax) { loadKV(kt + 1, cur ^ 1); CP_COMMIT(); }

        const __half* Ks = Kst + cur * K2_ELEM;
        const __half* Vs = Vst + cur * VT_ELEM;

        float s[8][4];
        #pragma unroll
        for (int jn = 0; jn < 8; jn++)
            #pragma unroll
            for (int q = 0; q < 4; q++) s[jn][q] = 0.f;

        #pragma unroll
        for (int j = 0; j < 24; j++) {
            const int qoff = (j < 16) ? (j & 7) * 16 : 128 + (j - 16) * 16;
            const int koff = (j < 8) ? j * 16 : ((j < 16) ? 128 + (j - 8) * 16 : (j - 16) * 16);
            const __half* qa = Qs + (w * 16 + r0) * AQ_STR + qoff + c0;
            uint32_t a0 = *(const uint32_t*)qa;
            uint32_t a1 = *(const uint32_t*)(qa + 8 * AQ_STR);
            uint32_t a2 = *(const uint32_t*)(qa + 8);
            uint32_t a3 = *(const uint32_t*)(qa + 8 * AQ_STR + 8);
            #pragma unroll
            for (int jn = 0; jn < 8; jn++) {
                const __half* kb = Ks + (jn * 8 + r0) * AQ_STR + koff + c0;
                uint32_t b0 = *(const uint32_t*)kb;
                uint32_t b1 = *(const uint32_t*)(kb + 8);
                MMAF16(s[jn][0], s[jn][1], s[jn][2], s[jn][3], a0, a1, a2, a3, b0, b1);
            }
        }

        float rm0 = -INFINITY, rm1 = -INFINITY;
        #pragma unroll
        for (int jn = 0; jn < 8; jn++) {
            int gcol = kt * 64 + jn * 8 + c0;
            s[jn][0] = (gcol     > grow0) ? -INFINITY : s[jn][0] * scale;
            s[jn][1] = (gcol + 1 > grow0) ? -INFINITY : s[jn][1] * scale;
            s[jn][2] = (gcol     > grow1) ? -INFINITY : s[jn][2] * scale;
            s[jn][3] = (gcol + 1 > grow1) ? -INFINITY : s[jn][3] * scale;
            rm0 = fmaxf(rm0, fmaxf(s[jn][0], s[jn][1]));
            rm1 = fmaxf(rm1, fmaxf(s[jn][2], s[jn][3]));
        }
        rm0 = fmaxf(rm0, __shfl_xor_sync(0xffffffffu, rm0, 1));
        rm0 = fmaxf(rm0, __shfl_xor_sync(0xffffffffu, rm0, 2));
        rm1 = fmaxf(rm1, __shfl_xor_sync(0xffffffffu, rm1, 1));
        rm1 = fmaxf(rm1, __shfl_xor_sync(0xffffffffu, rm1, 2));

        float mn0 = fmaxf(m_i[0], rm0), mn1 = fmaxf(m_i[1], rm1);
        float f0 = __expf(m_i[0] - mn0), f1 = __expf(m_i[1] - mn1);
        float ps0 = 0.f, ps1 = 0.f;
        #pragma unroll
        for (int jn = 0; jn < 8; jn++) {
            s[jn][0] = __expf(s[jn][0] - mn0);
            s[jn][1] = __expf(s[jn][1] - mn0);
            s[jn][2] = __expf(s[jn][2] - mn1);
            s[jn][3] = __expf(s[jn][3] - mn1);
            ps0 += s[jn][0] + s[jn][1];
            ps1 += s[jn][2] + s[jn][3];
        }
        ps0 += __shfl_xor_sync(0xffffffffu, ps0, 1);
        ps0 += __shfl_xor_sync(0xffffffffu, ps0, 2);
        ps1 += __shfl_xor_sync(0xffffffffu, ps1, 1);
        ps1 += __shfl_xor_sync(0xffffffffu, ps1, 2);
        l_i[0] = l_i[0] * f0 + ps0;  m_i[0] = mn0;
        l_i[1] = l_i[1] * f1 + ps1;  m_i[1] = mn1;
        #pragma unroll
        for (int j = 0; j < 16; j++) {
            o[j][0] *= f0; o[j][1] *= f0; o[j][2] *= f1; o[j][3] *= f1;
        }

        #pragma unroll
        for (int kt2 = 0; kt2 < 4; kt2++) {
            union { __half2 h; uint32_t u; } pa0, pa1, pa2, pa3;
            pa0.h = __floats2half2_rn(s[2*kt2][0],     s[2*kt2][1]);
            pa1.h = __floats2half2_rn(s[2*kt2][2],     s[2*kt2][3]);
            pa2.h = __floats2half2_rn(s[2*kt2 + 1][0], s[2*kt2 + 1][1]);
            pa3.h = __floats2half2_rn(s[2*kt2 + 1][2], s[2*kt2 + 1][3]);
            #pragma unroll
            for (int jn2 = 0; jn2 < 16; jn2++) {
                const __half* vb = Vs + (jn2 * 8 + r0) * AV_STR + kt2 * 16 + c0;
                uint32_t b0 = *(const uint32_t*)vb;
                uint32_t b1 = *(const uint32_t*)(vb + 8);
                MMAF16(o[jn2][0], o[jn2][1], o[jn2][2], o[jn2][3],
                       pa0.u, pa1.u, pa2.u, pa3.u, b0, b1);
            }
        }
    }

    float inv0 = 1.f / l_i[0], inv1 = 1.f / l_i[1];
    size_t row0 = (size_t)(b * SEQ + grow0);
    size_t row1 = (size_t)(b * SEQ + grow1);
    #pragma unroll
    for (int jn2 = 0; jn2 < 16; jn2++) {
        int hd = head * HD + jn2 * 8 + c0;
        float v00 = o[jn2][0] * inv0, v01 = o[jn2][1] * inv0;
        float v10 = o[jn2][2] * inv1, v11 = o[jn2][3] * inv1;

        union { __half b[2]; uint32_t u; } hi, lo;
        __half h0, h1;

        h0 = __float2half(v00); h1 = __float2half(v01);
        hi.b[0] = h0; hi.b[1] = h1;
        lo.b[0] = __float2half(v00 - __half2float(h0));
        lo.b[1] = __float2half(v01 - __half2float(h1));
        size_t base0 = row0 * (2 * DIM) + hd;
        *(uint32_t*)&attn2[base0]       = hi.u;
        *(uint32_t*)&attn2[base0 + DIM] = lo.u;

        h0 = __float2half(v10); h1 = __float2half(v11);
        hi.b[0] = h0; hi.b[1] = h1;
        lo.b[0] = __float2half(v10 - __half2float(h0));
        lo.b[1] = __float2half(v11 - __half2float(h1));
        size_t base1 = row1 * (2 * DIM) + hd;
        *(uint32_t*)&attn2[base1]       = hi.u;
        *(uint32_t*)&attn2[base1 + DIM] = lo.u;
    }
}

// ---------------------------------------------------------------------------
// launcher
// ---------------------------------------------------------------------------
extern "C" void kernel_launch(void* const* d_in, const int* in_sizes, int n_in,
                              void* d_out, int out_size)
{
    const float* x     = (const float*)d_in[0];
    const float* freqs = (const float*)d_in[1];
    const float* Wqkv  = (const float*)d_in[2];
    const float* Wout  = (const float*)d_in[3];
    float* out = (float*)d_out;

    __half *x2, *wqkv1, *attn2, *wout1, *q2, *k2, *vt;
    cudaGetSymbolAddress((void**)&x2,    g_x2);
    cudaGetSymbolAddress((void**)&wqkv1, g_wqkv1);
    cudaGetSymbolAddress((void**)&attn2, g_attn2);
    cudaGetSymbolAddress((void**)&wout1, g_wout1);
    cudaGetSymbolAddress((void**)&q2,    g_q2);
    cudaGetSymbolAddress((void**)&k2,    g_k2);
    cudaGetSymbolAddress((void**)&vt,    g_vt);

    cudaFuncSetAttribute(gemm_mma_kernel,
                         cudaFuncAttributeMaxDynamicSharedMemorySize, GEMM_SMEM);
    cudaFuncSetAttribute(attn_tc_kernel,
                         cudaFuncAttributeMaxDynamicSharedMemorySize, ATTN_SMEM);

    // 1) operand conversions
    split2_kernel<<<(M_TOT * (DIM/4)) / 256, 256>>>(x,    x2,    DIM);
    split1_kernel<<<(QKV_N * (DIM/4)) / 256, 256>>>(Wqkv, wqkv1, DIM);

    // 2) QKV projection + fused RoPE/split epilogue (mode 1)
    gemm_mma_kernel<<<dim3(QKV_N/128, M_TOT/128), 256, GEMM_SMEM>>>(
        x2, wqkv1, nullptr, 0, 1, freqs, q2, k2, vt);

    // 3) tensor-core causal flash attention -> g_attn2 (fp16 2-split)
    attn_tc_kernel<<<dim3(SEQ/128, NH, BATCH), 256, ATTN_SMEM>>>(q2, k2, vt, attn2);

    // 4) weight conversion for stage-2 GEMM
    split1_kernel<<<(DIM * (DIM/4)) / 256, 256>>>(Wout, wout1, DIM);

    // 5) output projection (mode 0)
    gemm_mma_kernel<<<dim3(DIM/128, M_TOT/128), 256, GEMM_SMEM>>>(
        attn2, wout1, out, DIM, 0, nullptr, nullptr, nullptr, nullptr);
}